// round 2
// baseline (speedup 1.0000x reference)
#include <cuda_runtime.h>
#include <math.h>

#define SCALE 0.088388347648318447f  // 1/sqrt(128)

// ---- static scratch (allocation-free) ----
__device__ float g_K  [16777216];   // [b,h,j,d]   K projection
__device__ float g_Vt [16777216];   // [b,h,d,j]   V projection, transposed for PV-GEMM
__device__ float g_QU [8388608];    // [b,h,i,d]   q + u
__device__ float g_QV [8388608];    // [b,h,i,d]   q + v
__device__ float g_P  [1048576];    // [h,jj,d]    pos projection
__device__ float g_PE [131072];     // [jj,e]      sinusoidal table
__device__ float g_S1 [67108864];   // [bh,i,j]    content scores -> probs
__device__ float g_S2 [67108864];   // [bh,i,jj]   position scores (pre-shift)
__device__ float g_O  [8388608];    // [i*B+b, h*128+d]

// ---- positional embedding table ----
__global__ void pe_fill() {
    int idx = blockIdx.x * blockDim.x + threadIdx.x;
    if (idx >= 65536) return;
    int jj = idx >> 6, e2 = idx & 63;
    double pos  = (double)(1023 - jj);
    double invf = exp(-((double)e2 / 64.0) * log(10000.0));
    double ang  = pos * invf;
    g_PE[jj * 128 + e2]      = (float)sin(ang);
    g_PE[jj * 128 + 64 + e2] = (float)cos(ang);
}

// ---- generic NT GEMM: C[M,N] = A[M,K] * W[N,K]^T, mode-specific A source + epilogue ----
// MODE 0: kv proj  (A = [memory[0]; inputs], W=w_kv, scatter to g_K / g_Vt)
// MODE 1: q proj   (A = inputs, W=w_q, write g_QU=+u, g_QV=+v)
// MODE 2: p proj   (A = g_PE, W=w_p, scatter to g_P)
// MODE 3: content  (batched bh: A=g_QU, W=g_K  -> g_S1)
// MODE 4: position (batched bh: A=g_QV, W=g_P[h] -> g_S2)
// MODE 5: PV       (batched bh: A=probs(g_S1), W=g_Vt -> g_O)
// MODE 6: out proj (A = g_O, W=w_out -> d_out twice)
template<int MODE>
__global__ void __launch_bounds__(256) gemm_k(
    const float* __restrict__ inputs, const float* __restrict__ mem0,
    const float* __restrict__ Wext, const float* __restrict__ uu,
    const float* __restrict__ vv, float* __restrict__ dout, int writeAux)
{
    constexpr int K = (MODE >= 5) ? 1024 : 128;
    const int z  = blockIdx.z;
    const int m0 = blockIdx.y * 64, n0 = blockIdx.x * 64;
    const int tid = threadIdx.x;
    const int tx = tid & 15, ty = tid >> 4;

    const float* Abase = nullptr;
    const float* Wbase = Wext;
    if (MODE == 1) Abase = inputs;
    if (MODE == 2) Abase = g_PE;
    if (MODE == 3) { Abase = g_QU + (size_t)z * 65536;  Wbase = g_K  + (size_t)z * 131072; }
    if (MODE == 4) { Abase = g_QV + (size_t)z * 65536;  Wbase = g_P  + (size_t)(z & 7) * 131072; }
    if (MODE == 5) { Abase = g_S1 + (size_t)z * 524288; Wbase = g_Vt + (size_t)z * 131072; }
    if (MODE == 6) { Abase = g_O; }

    __shared__ float As[32][65];
    __shared__ float Ws[32][65];
    float acc[4][4];
#pragma unroll
    for (int a = 0; a < 4; ++a)
#pragma unroll
        for (int b = 0; b < 4; ++b) acc[a][b] = 0.f;

    for (int kc = 0; kc < K; kc += 32) {
#pragma unroll
        for (int it = 0; it < 2; ++it) {
            int q   = tid + it * 256;
            int row = q >> 3, c4 = q & 7;
            int r = m0 + row;
            const float* Ap;
            if (MODE == 0)
                Ap = (r < 8192) ? (mem0 + (size_t)r * 128)
                                : (inputs + (size_t)(r - 8192) * 128);
            else
                Ap = Abase + (size_t)r * K;
            float4 av = *(const float4*)(Ap + kc + c4 * 4);
            As[c4 * 4 + 0][row] = av.x; As[c4 * 4 + 1][row] = av.y;
            As[c4 * 4 + 2][row] = av.z; As[c4 * 4 + 3][row] = av.w;
            float4 wv = *(const float4*)(Wbase + (size_t)(n0 + row) * K + kc + c4 * 4);
            Ws[c4 * 4 + 0][row] = wv.x; Ws[c4 * 4 + 1][row] = wv.y;
            Ws[c4 * 4 + 2][row] = wv.z; Ws[c4 * 4 + 3][row] = wv.w;
        }
        __syncthreads();
#pragma unroll
        for (int k = 0; k < 32; ++k) {
            float a0 = As[k][ty * 4 + 0], a1 = As[k][ty * 4 + 1];
            float a2 = As[k][ty * 4 + 2], a3 = As[k][ty * 4 + 3];
            float b0 = Ws[k][tx * 4 + 0], b1 = Ws[k][tx * 4 + 1];
            float b2 = Ws[k][tx * 4 + 2], b3 = Ws[k][tx * 4 + 3];
            acc[0][0] += a0 * b0; acc[0][1] += a0 * b1; acc[0][2] += a0 * b2; acc[0][3] += a0 * b3;
            acc[1][0] += a1 * b0; acc[1][1] += a1 * b1; acc[1][2] += a1 * b2; acc[1][3] += a1 * b3;
            acc[2][0] += a2 * b0; acc[2][1] += a2 * b1; acc[2][2] += a2 * b2; acc[2][3] += a2 * b3;
            acc[3][0] += a3 * b0; acc[3][1] += a3 * b1; acc[3][2] += a3 * b2; acc[3][3] += a3 * b3;
        }
        __syncthreads();
    }

#pragma unroll
    for (int ii = 0; ii < 4; ++ii) {
        int r = m0 + ty * 4 + ii;
#pragma unroll
        for (int jn = 0; jn < 4; ++jn) {
            int n = n0 + tx * 4 + jn;
            float val = acc[ii][jn];
            if (MODE == 0) {
                int j = r >> 4, b = r & 15;
                if (n < 1024) {
                    int h = n >> 7, d = n & 127;
                    g_K[(size_t)((b * 8 + h) * 1024 + j) * 128 + d] = val;
                } else {
                    int n2 = n - 1024; int h = n2 >> 7, d = n2 & 127;
                    g_Vt[(size_t)((b * 8 + h) * 128 + d) * 1024 + j] = val;
                }
            } else if (MODE == 1) {
                int i = r >> 4, b = r & 15;
                size_t base = (size_t)((b * 8 + (n >> 7)) * 512 + i) * 128 + (n & 127);
                g_QU[base] = val + uu[n];
                g_QV[base] = val + vv[n];
            } else if (MODE == 2) {
                g_P[(size_t)((n >> 7) * 1024 + r) * 128 + (n & 127)] = val;
            } else if (MODE == 3) {
                g_S1[(size_t)z * 524288 + (size_t)r * 1024 + n] = val;
            } else if (MODE == 4) {
                g_S2[(size_t)z * 524288 + (size_t)r * 1024 + n] = val;
            } else if (MODE == 5) {
                int b = z >> 3, h = z & 7;
                g_O[(size_t)(r * 16 + b) * 1024 + h * 128 + n] = val;
            } else {  // MODE 6
                dout[(size_t)r * 128 + n] = val;
                if (writeAux) dout[2097152 + (size_t)r * 128 + n] = val;
            }
        }
    }
}

// ---- masked softmax with fused rel-shift: prob = softmax_j( (S1[i,j] + S2[i,511+j-i]) * scale ) ----
__global__ void __launch_bounds__(256) softmax_k() {
    int i = blockIdx.x;          // query row 0..511
    int bh = blockIdx.y;         // 0..127
    float* S1 = g_S1 + ((size_t)bh * 512 + i) * 1024;
    const float* S2 = g_S2 + ((size_t)bh * 512 + i) * 1024;
    int jmax = i + 512;          // inclusive attend limit
    int tid = threadIdx.x;

    float vals[4];
    float vmax = -1e30f;
#pragma unroll
    for (int q = 0; q < 4; ++q) {
        int j = tid + q * 256;
        float s = -1e30f;
        if (j <= jmax) s = (S1[j] + S2[511 + j - i]) * SCALE;
        vals[q] = s;
        vmax = fmaxf(vmax, s);
    }
    __shared__ float red[256];
    red[tid] = vmax; __syncthreads();
    for (int s = 128; s > 0; s >>= 1) {
        if (tid < s) red[tid] = fmaxf(red[tid], red[tid + s]);
        __syncthreads();
    }
    vmax = red[0]; __syncthreads();

    float lsum = 0.f;
#pragma unroll
    for (int q = 0; q < 4; ++q) { vals[q] = __expf(vals[q] - vmax); lsum += vals[q]; }
    red[tid] = lsum; __syncthreads();
    for (int s = 128; s > 0; s >>= 1) {
        if (tid < s) red[tid] += red[tid + s];
        __syncthreads();
    }
    float inv = 1.f / red[0];
#pragma unroll
    for (int q = 0; q < 4; ++q) {
        int j = tid + q * 256;
        S1[j] = vals[q] * inv;   // masked lanes underflow to exactly 0
    }
}

// ---- copy inputs into new_mem[0] slot ----
__global__ void copy_k(const float* __restrict__ src, float* __restrict__ dst) {
    int idx = blockIdx.x * blockDim.x + threadIdx.x;
    ((float4*)dst)[idx] = ((const float4*)src)[idx];
}

extern "C" void kernel_launch(void* const* d_in, const int* in_sizes, int n_in,
                              void* d_out, int out_size) {
    const float* inputs = (const float*)d_in[0];
    const float* memory = (const float*)d_in[1];   // [2,P,B,D]; layer 0 = first half
    const float* w_kv   = (const float*)d_in[2];
    const float* w_q    = (const float*)d_in[3];
    const float* w_p    = (const float*)d_in[4];
    const float* w_out  = (const float*)d_in[5];
    const float* u      = (const float*)d_in[6];
    const float* v      = (const float*)d_in[7];
    float* out = (float*)d_out;

    // output = [layer_out | inputs | layer_out] (new_mem degenerates since cs==ps)
    int writeAux = (out_size >= 3 * 1048576) ? 1 : 0;

    pe_fill<<<256, 256>>>();
    // kv projection: M=16384 (J*B), N=2048
    gemm_k<0><<<dim3(32, 256, 1), 256>>>(inputs, memory, w_kv, nullptr, nullptr, nullptr, 0);
    // q projection: M=8192 (T*B), N=1024
    gemm_k<1><<<dim3(16, 128, 1), 256>>>(inputs, nullptr, w_q, u, v, nullptr, 0);
    // p projection: M=1024 (J), N=1024
    gemm_k<2><<<dim3(16, 16, 1), 256>>>(inputs, nullptr, w_p, nullptr, nullptr, nullptr, 0);
    // content scores, batched over bh=128: M=512, N=1024
    gemm_k<3><<<dim3(16, 8, 128), 256>>>(inputs, nullptr, nullptr, nullptr, nullptr, nullptr, 0);
    // position scores, batched: M=512, N=1024
    gemm_k<4><<<dim3(16, 8, 128), 256>>>(inputs, nullptr, nullptr, nullptr, nullptr, nullptr, 0);
    // softmax + rel-shift + mask, one block per (i, bh)
    softmax_k<<<dim3(512, 128), 256>>>();
    // PV, batched: M=512, N=128, K=1024
    gemm_k<5><<<dim3(2, 8, 128), 256>>>(inputs, nullptr, nullptr, nullptr, nullptr, nullptr, 0);
    // output projection: M=8192, N=128, K=1024, writes layer_out (twice)
    gemm_k<6><<<dim3(2, 128, 1), 256>>>(inputs, nullptr, w_out, nullptr, nullptr, out, writeAux);
    if (writeAux) copy_k<<<1024, 256>>>(inputs, out + 1048576);
}

// round 3
// speedup vs baseline: 2.5447x; 2.5447x over previous
#include <cuda_runtime.h>
#include <math.h>
#include <stdint.h>

#define SCALE 0.088388347648318447f  // 1/sqrt(128)

// ---- static scratch (allocation-free) ----
__device__ float g_K  [16777216];   // [b,h,j,d]
__device__ float g_Vt [16777216];   // [b,h,d,j]
__device__ float g_QU [8388608];    // [b,h,i,d]
__device__ float g_QV [8388608];    // [b,h,i,d]
__device__ float g_P  [1048576];    // [h,jj,d]
__device__ float g_PE [131072];     // [jj,e]
__device__ float g_S1 [67108864];   // [bh,i,j]  content -> probs
__device__ float g_S2 [67108864];   // [bh,i,jj] position (pre-shift)
__device__ float g_O  [8388608];    // [i*B+b, h*128+d]

__global__ void pe_fill() {
    int idx = blockIdx.x * blockDim.x + threadIdx.x;
    if (idx >= 65536) return;
    int jj = idx >> 6, e2 = idx & 63;
    double pos  = (double)(1023 - jj);
    double invf = exp(-((double)e2 / 64.0) * log(10000.0));
    double ang  = pos * invf;
    g_PE[jj * 128 + e2]      = (float)sin(ang);
    g_PE[jj * 128 + 64 + e2] = (float)cos(ang);
}

__device__ __forceinline__ uint32_t f2tf(float x) {
    uint32_t r; asm("cvt.rna.tf32.f32 %0, %1;" : "=r"(r) : "f"(x)); return r;
}
__device__ __forceinline__ void ldsm4(uint32_t& r0, uint32_t& r1, uint32_t& r2, uint32_t& r3, uint32_t addr) {
    asm volatile("ldmatrix.sync.aligned.m8n8.x4.shared.b16 {%0,%1,%2,%3}, [%4];"
                 : "=r"(r0), "=r"(r1), "=r"(r2), "=r"(r3) : "r"(addr));
}
__device__ __forceinline__ void mma8(float* c, const uint32_t* a, uint32_t b0, uint32_t b1) {
    asm volatile("mma.sync.aligned.m16n8k8.row.col.f32.tf32.tf32.f32 "
                 "{%0,%1,%2,%3},{%4,%5,%6,%7},{%8,%9},{%0,%1,%2,%3};"
                 : "+f"(c[0]), "+f"(c[1]), "+f"(c[2]), "+f"(c[3])
                 : "r"(a[0]), "r"(a[1]), "r"(a[2]), "r"(a[3]), "r"(b0), "r"(b1));
}

// ---- tensor-core NT GEMM: C[M,N] = A[M,K] * W[N,K]^T ----
// BM=128, BN=64, BK=32; 8 warps, each 32x32 via m16n8k8 tf32.
template<int MODE>
__global__ void __launch_bounds__(256) gemm_k(
    const float* __restrict__ inputs, const float* __restrict__ mem0,
    const float* __restrict__ Wext, const float* __restrict__ uu,
    const float* __restrict__ vv, float* __restrict__ dout, int writeAux)
{
    constexpr int K   = (MODE >= 5) ? 1024 : 128;
    constexpr int KIT = K / 32;
    const int z  = blockIdx.z;
    const int m0 = blockIdx.y * 128, n0 = blockIdx.x * 64;
    const int tid = threadIdx.x;
    const int lane = tid & 31, w = tid >> 5;
    const int wm = w >> 1, wn = w & 1;

    const float* Abase = nullptr;
    const float* Wbase = Wext;
    if (MODE == 1) Abase = inputs;
    if (MODE == 2) Abase = g_PE;
    if (MODE == 3) { Abase = g_QU + (size_t)z * 65536;  Wbase = g_K  + (size_t)z * 131072; }
    if (MODE == 4) { Abase = g_QV + (size_t)z * 65536;  Wbase = g_P  + (size_t)(z & 7) * 131072; }
    if (MODE == 5) { Abase = g_S1 + (size_t)z * 524288; Wbase = g_Vt + (size_t)z * 131072; }
    if (MODE == 6) { Abase = g_O; }

    __shared__ uint32_t As[4096];  // 128 x 32 tf32, xor-swizzled 16B chunks
    __shared__ uint32_t Bs[2048];  // 64  x 32
    uint32_t as_addr = (uint32_t)__cvta_generic_to_shared(As);
    uint32_t bs_addr = (uint32_t)__cvta_generic_to_shared(Bs);

    float acc[2][4][4];
#pragma unroll
    for (int a = 0; a < 2; ++a)
#pragma unroll
        for (int b = 0; b < 4; ++b)
#pragma unroll
            for (int c = 0; c < 4; ++c) acc[a][b][c] = 0.f;

    float4 pa[4], pb[2];

    auto loadA = [&](int it) {
#pragma unroll
        for (int i = 0; i < 4; ++i) {
            int idx = tid + i * 256;
            int row = idx >> 3, ch = idx & 7;
            int r = m0 + row;
            const float* Ap;
            if (MODE == 0)
                Ap = (r < 8192) ? (mem0 + (size_t)r * 128)
                                : (inputs + (size_t)(r - 8192) * 128);
            else
                Ap = Abase + (size_t)r * K;
            pa[i] = *(const float4*)(Ap + it * 32 + ch * 4);
        }
    };
    auto loadB = [&](int it) {
#pragma unroll
        for (int i = 0; i < 2; ++i) {
            int idx = tid + i * 256;
            int row = idx >> 3, ch = idx & 7;
            pb[i] = *(const float4*)(Wbase + (size_t)(n0 + row) * K + it * 32 + ch * 4);
        }
    };
    auto stage = [&]() {
#pragma unroll
        for (int i = 0; i < 4; ++i) {
            int idx = tid + i * 256;
            int row = idx >> 3, ch = idx & 7;
            uint32_t off = row * 32 + ((ch ^ (row & 7)) << 2);
            *(uint4*)&As[off] = make_uint4(f2tf(pa[i].x), f2tf(pa[i].y), f2tf(pa[i].z), f2tf(pa[i].w));
        }
#pragma unroll
        for (int i = 0; i < 2; ++i) {
            int idx = tid + i * 256;
            int row = idx >> 3, ch = idx & 7;
            uint32_t off = row * 32 + ((ch ^ (row & 7)) << 2);
            *(uint4*)&Bs[off] = make_uint4(f2tf(pb[i].x), f2tf(pb[i].y), f2tf(pb[i].z), f2tf(pb[i].w));
        }
    };

    loadA(0); loadB(0);
    stage();
    __syncthreads();

    const int lrow = lane & 7, lm = lane >> 3;
    for (int it = 0; it < KIT; ++it) {
        if (it + 1 < KIT) { loadA(it + 1); loadB(it + 1); }
#pragma unroll
        for (int ks = 0; ks < 4; ++ks) {
            uint32_t afr[2][4], bfr[2][4];
#pragma unroll
            for (int mi = 0; mi < 2; ++mi) {
                int row = wm * 32 + mi * 16 + ((lm & 1) << 3) + lrow;
                int ch  = ks * 2 + (lm >> 1);
                ldsm4(afr[mi][0], afr[mi][1], afr[mi][2], afr[mi][3],
                      as_addr + ((row * 32 + ((ch ^ lrow) << 2)) << 2));
            }
#pragma unroll
            for (int np = 0; np < 2; ++np) {
                int row = wn * 32 + np * 16 + ((lm >> 1) << 3) + lrow;
                int ch  = ks * 2 + (lm & 1);
                ldsm4(bfr[np][0], bfr[np][1], bfr[np][2], bfr[np][3],
                      bs_addr + ((row * 32 + ((ch ^ lrow) << 2)) << 2));
            }
#pragma unroll
            for (int mi = 0; mi < 2; ++mi)
#pragma unroll
                for (int nj = 0; nj < 4; ++nj)
                    mma8(acc[mi][nj], afr[mi], bfr[nj >> 1][(nj & 1) * 2], bfr[nj >> 1][(nj & 1) * 2 + 1]);
        }
        __syncthreads();
        if (it + 1 < KIT) { stage(); __syncthreads(); }
    }

    // ---- epilogue ----
    const int r0l = lane >> 2, c0l = (lane & 3) * 2;
#pragma unroll
    for (int mi = 0; mi < 2; ++mi)
#pragma unroll
        for (int nj = 0; nj < 4; ++nj)
#pragma unroll
            for (int e = 0; e < 4; ++e) {
                int r = m0 + wm * 32 + mi * 16 + r0l + ((e >= 2) ? 8 : 0);
                int n = n0 + wn * 32 + nj * 8 + c0l + (e & 1);
                float val = acc[mi][nj][e];
                if (MODE == 0) {
                    int j = r >> 4, b = r & 15;
                    if (n < 1024) {
                        int h = n >> 7, d = n & 127;
                        g_K[(size_t)((b * 8 + h) * 1024 + j) * 128 + d] = val;
                    } else {
                        int n2 = n - 1024; int h = n2 >> 7, d = n2 & 127;
                        g_Vt[(size_t)((b * 8 + h) * 128 + d) * 1024 + j] = val;
                    }
                } else if (MODE == 1) {
                    int i = r >> 4, b = r & 15;
                    size_t base = (size_t)((b * 8 + (n >> 7)) * 512 + i) * 128 + (n & 127);
                    g_QU[base] = val + uu[n];
                    g_QV[base] = val + vv[n];
                } else if (MODE == 2) {
                    g_P[(size_t)((n >> 7) * 1024 + r) * 128 + (n & 127)] = val;
                } else if (MODE == 3) {
                    g_S1[(size_t)z * 524288 + (size_t)r * 1024 + n] = val;
                } else if (MODE == 4) {
                    g_S2[(size_t)z * 524288 + (size_t)r * 1024 + n] = val;
                } else if (MODE == 5) {
                    int b = z >> 3, h = z & 7;
                    g_O[(size_t)(r * 16 + b) * 1024 + h * 128 + n] = val;
                } else {  // MODE 6
                    dout[(size_t)r * 128 + n] = val;
                    if (writeAux) dout[2097152 + (size_t)r * 128 + n] = val;
                }
            }
}

// ---- masked softmax with fused rel-shift ----
__global__ void __launch_bounds__(256) softmax_k() {
    int i = blockIdx.x;
    int bh = blockIdx.y;
    float* S1 = g_S1 + ((size_t)bh * 512 + i) * 1024;
    const float* S2 = g_S2 + ((size_t)bh * 512 + i) * 1024;
    int jmax = i + 512;
    int tid = threadIdx.x;

    float vals[4];
    float vmax = -1e30f;
#pragma unroll
    for (int q = 0; q < 4; ++q) {
        int j = tid + q * 256;
        float s = -1e30f;
        if (j <= jmax) s = (S1[j] + S2[511 + j - i]) * SCALE;
        vals[q] = s;
        vmax = fmaxf(vmax, s);
    }
    __shared__ float red[256];
    red[tid] = vmax; __syncthreads();
    for (int s = 128; s > 0; s >>= 1) {
        if (tid < s) red[tid] = fmaxf(red[tid], red[tid + s]);
        __syncthreads();
    }
    vmax = red[0]; __syncthreads();

    float lsum = 0.f;
#pragma unroll
    for (int q = 0; q < 4; ++q) { vals[q] = __expf(vals[q] - vmax); lsum += vals[q]; }
    red[tid] = lsum; __syncthreads();
    for (int s = 128; s > 0; s >>= 1) {
        if (tid < s) red[tid] += red[tid + s];
        __syncthreads();
    }
    float inv = 1.f / red[0];
#pragma unroll
    for (int q = 0; q < 4; ++q) {
        int j = tid + q * 256;
        S1[j] = vals[q] * inv;
    }
}

__global__ void copy_k(const float* __restrict__ src, float* __restrict__ dst) {
    int idx = blockIdx.x * blockDim.x + threadIdx.x;
    ((float4*)dst)[idx] = ((const float4*)src)[idx];
}

extern "C" void kernel_launch(void* const* d_in, const int* in_sizes, int n_in,
                              void* d_out, int out_size) {
    const float* inputs = (const float*)d_in[0];
    const float* memory = (const float*)d_in[1];
    const float* w_kv   = (const float*)d_in[2];
    const float* w_q    = (const float*)d_in[3];
    const float* w_p    = (const float*)d_in[4];
    const float* w_out  = (const float*)d_in[5];
    const float* u      = (const float*)d_in[6];
    const float* v      = (const float*)d_in[7];
    float* out = (float*)d_out;

    int writeAux = (out_size >= 3 * 1048576) ? 1 : 0;

    pe_fill<<<256, 256>>>();
    // kv proj: M=16384, N=2048, K=128
    gemm_k<0><<<dim3(32, 128, 1), 256>>>(inputs, memory, w_kv, nullptr, nullptr, nullptr, 0);
    // q proj: M=8192, N=1024, K=128
    gemm_k<1><<<dim3(16, 64, 1), 256>>>(inputs, nullptr, w_q, u, v, nullptr, 0);
    // p proj: M=1024, N=1024, K=128
    gemm_k<2><<<dim3(16, 8, 1), 256>>>(inputs, nullptr, w_p, nullptr, nullptr, nullptr, 0);
    // content scores: M=512, N=1024, K=128, z=128
    gemm_k<3><<<dim3(16, 4, 128), 256>>>(inputs, nullptr, nullptr, nullptr, nullptr, nullptr, 0);
    // position scores: M=512, N=1024, K=128, z=128
    gemm_k<4><<<dim3(16, 4, 128), 256>>>(inputs, nullptr, nullptr, nullptr, nullptr, nullptr, 0);
    // softmax + rel-shift + mask
    softmax_k<<<dim3(512, 128), 256>>>();
    // PV: M=512, N=128, K=1024, z=128
    gemm_k<5><<<dim3(2, 4, 128), 256>>>(inputs, nullptr, nullptr, nullptr, nullptr, nullptr, 0);
    // out proj: M=8192, N=128, K=1024
    gemm_k<6><<<dim3(2, 64, 1), 256>>>(inputs, nullptr, w_out, nullptr, nullptr, out, writeAux);
    if (writeAux) copy_k<<<1024, 256>>>(inputs, out + 1048576);
}

// round 4
// speedup vs baseline: 3.2101x; 1.2615x over previous
#include <cuda_runtime.h>
#include <math.h>
#include <stdint.h>

#define SCALE 0.088388347648318447f  // 1/sqrt(128)

// ---- static scratch (allocation-free) ----
__device__ float g_K  [16777216];   // [b,h,j,d]
__device__ float g_Vt [16777216];   // [b,h,d,j]
__device__ float g_QU [8388608];    // [b,h,i,d]  q+u
__device__ float g_QV [8388608];    // [b,h,i,d]  q+v
__device__ float g_P  [1048576];    // [h,jj,d]
__device__ float g_PE [131072];     // [jj,e]
__device__ float g_S2 [67108864];   // [bh,i,j]   SHIFTED position scores (valid for j<=i+512)
__device__ float g_O  [8388608];    // [i*B+b, h*128+d]

__global__ void pe_fill() {
    int idx = blockIdx.x * blockDim.x + threadIdx.x;
    if (idx >= 65536) return;
    int jj = idx >> 6, e2 = idx & 63;
    double pos  = (double)(1023 - jj);
    double invf = exp(-((double)e2 / 64.0) * log(10000.0));
    double ang  = pos * invf;
    g_PE[jj * 128 + e2]      = (float)sin(ang);
    g_PE[jj * 128 + 64 + e2] = (float)cos(ang);
}

__device__ __forceinline__ uint32_t f2tf(float x) {
    uint32_t r; asm("cvt.rna.tf32.f32 %0, %1;" : "=r"(r) : "f"(x)); return r;
}
__device__ __forceinline__ void ldsm4(uint32_t& r0, uint32_t& r1, uint32_t& r2, uint32_t& r3, uint32_t addr) {
    asm volatile("ldmatrix.sync.aligned.m8n8.x4.shared.b16 {%0,%1,%2,%3}, [%4];"
                 : "=r"(r0), "=r"(r1), "=r"(r2), "=r"(r3) : "r"(addr));
}
__device__ __forceinline__ void mma8(float* c, const uint32_t* a, uint32_t b0, uint32_t b1) {
    asm volatile("mma.sync.aligned.m16n8k8.row.col.f32.tf32.tf32.f32 "
                 "{%0,%1,%2,%3},{%4,%5,%6,%7},{%8,%9},{%0,%1,%2,%3};"
                 : "+f"(c[0]), "+f"(c[1]), "+f"(c[2]), "+f"(c[3])
                 : "r"(a[0]), "r"(a[1]), "r"(a[2]), "r"(a[3]), "r"(b0), "r"(b1));
}

// ---- tensor-core NT GEMM: C[M,N] = A[M,K] * W[N,K]^T ----
// MODE 0: kv proj   MODE 1: q proj   MODE 2: p proj
// MODE 4: position scores (epilogue applies rel-shift)   MODE 6: out proj
template<int MODE>
__global__ void __launch_bounds__(256) gemm_k(
    const float* __restrict__ inputs, const float* __restrict__ mem0,
    const float* __restrict__ Wext, const float* __restrict__ uu,
    const float* __restrict__ vv, float* __restrict__ dout, int writeAux)
{
    constexpr int K   = (MODE >= 5) ? 1024 : 128;
    constexpr int KIT = K / 32;
    const int z  = blockIdx.z;
    const int m0 = blockIdx.y * 128, n0 = blockIdx.x * 64;
    const int tid = threadIdx.x;
    const int lane = tid & 31, w = tid >> 5;
    const int wm = w >> 1, wn = w & 1;

    const float* Abase = nullptr;
    const float* Wbase = Wext;
    if (MODE == 1) Abase = inputs;
    if (MODE == 2) Abase = g_PE;
    if (MODE == 4) { Abase = g_QV + (size_t)z * 65536;  Wbase = g_P + (size_t)(z & 7) * 131072; }
    if (MODE == 6) { Abase = g_O; }

    __shared__ uint32_t As[4096];
    __shared__ uint32_t Bs[2048];
    uint32_t as_addr = (uint32_t)__cvta_generic_to_shared(As);
    uint32_t bs_addr = (uint32_t)__cvta_generic_to_shared(Bs);

    float acc[2][4][4];
#pragma unroll
    for (int a = 0; a < 2; ++a)
#pragma unroll
        for (int b = 0; b < 4; ++b)
#pragma unroll
            for (int c = 0; c < 4; ++c) acc[a][b][c] = 0.f;

    float4 pa[4], pb[2];

    auto loadA = [&](int it) {
#pragma unroll
        for (int i = 0; i < 4; ++i) {
            int idx = tid + i * 256;
            int row = idx >> 3, ch = idx & 7;
            int r = m0 + row;
            const float* Ap;
            if (MODE == 0)
                Ap = (r < 8192) ? (mem0 + (size_t)r * 128)
                                : (inputs + (size_t)(r - 8192) * 128);
            else
                Ap = Abase + (size_t)r * K;
            pa[i] = *(const float4*)(Ap + it * 32 + ch * 4);
        }
    };
    auto loadB = [&](int it) {
#pragma unroll
        for (int i = 0; i < 2; ++i) {
            int idx = tid + i * 256;
            int row = idx >> 3, ch = idx & 7;
            pb[i] = *(const float4*)(Wbase + (size_t)(n0 + row) * K + it * 32 + ch * 4);
        }
    };
    auto stage = [&]() {
#pragma unroll
        for (int i = 0; i < 4; ++i) {
            int idx = tid + i * 256;
            int row = idx >> 3, ch = idx & 7;
            uint32_t off = row * 32 + ((ch ^ (row & 7)) << 2);
            *(uint4*)&As[off] = make_uint4(f2tf(pa[i].x), f2tf(pa[i].y), f2tf(pa[i].z), f2tf(pa[i].w));
        }
#pragma unroll
        for (int i = 0; i < 2; ++i) {
            int idx = tid + i * 256;
            int row = idx >> 3, ch = idx & 7;
            uint32_t off = row * 32 + ((ch ^ (row & 7)) << 2);
            *(uint4*)&Bs[off] = make_uint4(f2tf(pb[i].x), f2tf(pb[i].y), f2tf(pb[i].z), f2tf(pb[i].w));
        }
    };

    loadA(0); loadB(0);
    stage();
    __syncthreads();

    const int lrow = lane & 7, lm = lane >> 3;
    for (int it = 0; it < KIT; ++it) {
        if (it + 1 < KIT) { loadA(it + 1); loadB(it + 1); }
#pragma unroll
        for (int ks = 0; ks < 4; ++ks) {
            uint32_t afr[2][4], bfr[2][4];
#pragma unroll
            for (int mi = 0; mi < 2; ++mi) {
                int row = wm * 32 + mi * 16 + ((lm & 1) << 3) + lrow;
                int ch  = ks * 2 + (lm >> 1);
                ldsm4(afr[mi][0], afr[mi][1], afr[mi][2], afr[mi][3],
                      as_addr + ((row * 32 + ((ch ^ lrow) << 2)) << 2));
            }
#pragma unroll
            for (int np = 0; np < 2; ++np) {
                int row = wn * 32 + np * 16 + ((lm >> 1) << 3) + lrow;
                int ch  = ks * 2 + (lm & 1);
                ldsm4(bfr[np][0], bfr[np][1], bfr[np][2], bfr[np][3],
                      bs_addr + ((row * 32 + ((ch ^ lrow) << 2)) << 2));
            }
#pragma unroll
            for (int mi = 0; mi < 2; ++mi)
#pragma unroll
                for (int nj = 0; nj < 4; ++nj)
                    mma8(acc[mi][nj], afr[mi], bfr[nj >> 1][(nj & 1) * 2], bfr[nj >> 1][(nj & 1) * 2 + 1]);
        }
        __syncthreads();
        if (it + 1 < KIT) { stage(); __syncthreads(); }
    }

    // ---- epilogue ----
    const int r0l = lane >> 2, c0l = (lane & 3) * 2;
#pragma unroll
    for (int mi = 0; mi < 2; ++mi)
#pragma unroll
        for (int nj = 0; nj < 4; ++nj)
#pragma unroll
            for (int e = 0; e < 4; ++e) {
                int r = m0 + wm * 32 + mi * 16 + r0l + ((e >= 2) ? 8 : 0);
                int n = n0 + wn * 32 + nj * 8 + c0l + (e & 1);
                float val = acc[mi][nj][e];
                if (MODE == 0) {
                    int j = r >> 4, b = r & 15;
                    if (n < 1024) {
                        int h = n >> 7, d = n & 127;
                        g_K[(size_t)((b * 8 + h) * 1024 + j) * 128 + d] = val;
                    } else {
                        int n2 = n - 1024; int h = n2 >> 7, d = n2 & 127;
                        g_Vt[(size_t)((b * 8 + h) * 128 + d) * 1024 + j] = val;
                    }
                } else if (MODE == 1) {
                    int i = r >> 4, b = r & 15;
                    size_t base = (size_t)((b * 8 + (n >> 7)) * 512 + i) * 128 + (n & 127);
                    g_QU[base] = val + uu[n];
                    g_QV[base] = val + vv[n];
                } else if (MODE == 2) {
                    g_P[(size_t)((n >> 7) * 1024 + r) * 128 + (n & 127)] = val;
                } else if (MODE == 4) {
                    // rel-shift applied here: S2shift[i][j] = S2[i][511+j-i]
                    int j = n - 511 + r;
                    if (j >= 0 && j < 1024)
                        g_S2[(size_t)z * 524288 + (size_t)r * 1024 + j] = val;
                } else {  // MODE 6
                    dout[(size_t)r * 128 + n] = val;
                    if (writeAux) dout[2097152 + (size_t)r * 128 + n] = val;
                }
            }
}

// ---- fused flash attention: S1 = Q K^T, + S2shift, masked online softmax, O = P V ----
// grid (4 i-tiles, 128 bh), 256 threads (8 warps x 16 rows).
__global__ void __launch_bounds__(256, 1) flash_k() {
    extern __shared__ uint32_t sm[];
    uint32_t* sK = sm;            // [4 segs][64 rows][32]  (also Q staging)
    uint32_t* sV = sm + 8192;     // [2 segs][128 rows][32]
    uint32_t* sP = sm + 16384;    // [2 segs][128 rows][32]
    const uint32_t sKb = (uint32_t)__cvta_generic_to_shared(sK);
    const uint32_t sVb = (uint32_t)__cvta_generic_to_shared(sV);
    const uint32_t sPb = (uint32_t)__cvta_generic_to_shared(sP);

    const int bh = blockIdx.y;
    const int i0 = blockIdx.x * 128;
    const int tid = threadIdx.x, lane = tid & 31, w = tid >> 5;
    const int lrow = lane & 7, lm = lane >> 3;
    const int r0l = lane >> 2, c0l = (lane & 3) * 2;

    const float* Qb  = g_QU + (size_t)bh * 65536;
    const float* Kb  = g_K  + (size_t)bh * 131072;
    const float* Vb  = g_Vt + (size_t)bh * 131072;
    const float* S2b = g_S2 + (size_t)bh * 524288;

    uint32_t qf[4][4][4];

    // ---- load Q fragments via smem staging (two 64-row halves) ----
#pragma unroll
    for (int half = 0; half < 2; ++half) {
#pragma unroll
        for (int t = 0; t < 8; ++t) {
            int idx = tid + t * 256;
            int row = idx >> 5, f4 = idx & 31;
            int seg = f4 >> 3, ch = f4 & 7;
            float4 v = *(const float4*)(Qb + (size_t)(i0 + half * 64 + row) * 128 + f4 * 4);
            *(uint4*)&sK[seg * 2048 + row * 32 + ((ch ^ (row & 7)) << 2)] =
                make_uint4(f2tf(v.x), f2tf(v.y), f2tf(v.z), f2tf(v.w));
        }
        __syncthreads();
        if ((w >> 2) == half) {
            int wr = (w & 3) * 16;
#pragma unroll
            for (int kseg = 0; kseg < 4; ++kseg)
#pragma unroll
                for (int ks = 0; ks < 4; ++ks) {
                    int row = wr + ((lm & 1) << 3) + lrow;
                    int ch = ks * 2 + (lm >> 1);
                    ldsm4(qf[kseg][ks][0], qf[kseg][ks][1], qf[kseg][ks][2], qf[kseg][ks][3],
                          sKb + ((kseg * 2048 + row * 32 + ((ch ^ lrow) << 2)) << 2));
                }
        }
        __syncthreads();
    }

    float of[16][4];
#pragma unroll
    for (int a = 0; a < 16; ++a)
#pragma unroll
        for (int e = 0; e < 4; ++e) of[a][e] = 0.f;
    float mrow0 = -1e30f, mrow1 = -1e30f;
    float lrow0 = 0.f, lrow1 = 0.f;

    const int gi0 = i0 + w * 16 + r0l;
    const int gi1 = gi0 + 8;
    const int njt = 2 * blockIdx.x + 10;

    for (int jt = 0; jt < njt; ++jt) {
        int j0 = jt * 64;
        // load K tile (64 j-rows x 128 d)
#pragma unroll
        for (int t = 0; t < 8; ++t) {
            int idx = tid + t * 256;
            int row = idx >> 5, f4 = idx & 31;
            int seg = f4 >> 3, ch = f4 & 7;
            float4 v = *(const float4*)(Kb + (size_t)(j0 + row) * 128 + f4 * 4);
            *(uint4*)&sK[seg * 2048 + row * 32 + ((ch ^ (row & 7)) << 2)] =
                make_uint4(f2tf(v.x), f2tf(v.y), f2tf(v.z), f2tf(v.w));
        }
        // load V^T tile (128 d-rows x 64 j)
#pragma unroll
        for (int t = 0; t < 8; ++t) {
            int idx = tid + t * 256;
            int row = idx >> 4, f4 = idx & 15;
            int seg = f4 >> 3, ch = f4 & 7;
            float4 v = *(const float4*)(Vb + (size_t)row * 1024 + j0 + f4 * 4);
            *(uint4*)&sV[seg * 4096 + row * 32 + ((ch ^ (row & 7)) << 2)] =
                make_uint4(f2tf(v.x), f2tf(v.y), f2tf(v.z), f2tf(v.w));
        }
        __syncthreads();

        // scores: S = Q K^T (16 x 64 per warp)
        float sacc[8][4];
#pragma unroll
        for (int a = 0; a < 8; ++a)
#pragma unroll
            for (int e = 0; e < 4; ++e) sacc[a][e] = 0.f;
#pragma unroll
        for (int kseg = 0; kseg < 4; ++kseg)
#pragma unroll
            for (int ks = 0; ks < 4; ++ks) {
                uint32_t bfr[4][4];
#pragma unroll
                for (int nb = 0; nb < 4; ++nb) {
                    int row = nb * 16 + ((lm >> 1) << 3) + lrow;
                    int ch = ks * 2 + (lm & 1);
                    ldsm4(bfr[nb][0], bfr[nb][1], bfr[nb][2], bfr[nb][3],
                          sKb + ((kseg * 2048 + row * 32 + ((ch ^ lrow) << 2)) << 2));
                }
#pragma unroll
                for (int nf = 0; nf < 8; ++nf)
                    mma8(sacc[nf], qf[kseg][ks], bfr[nf >> 1][(nf & 1) * 2], bfr[nf >> 1][(nf & 1) * 2 + 1]);
            }

        // add shifted position scores, mask, scale, online softmax
        float mnew0 = mrow0, mnew1 = mrow1;
#pragma unroll
        for (int nf = 0; nf < 8; ++nf) {
            int jc = j0 + nf * 8 + c0l;
            float2 p0 = *(const float2*)(S2b + (size_t)gi0 * 1024 + jc);
            float2 p1 = *(const float2*)(S2b + (size_t)gi1 * 1024 + jc);
            float s00 = (sacc[nf][0] + p0.x) * SCALE;
            float s01 = (sacc[nf][1] + p0.y) * SCALE;
            float s10 = (sacc[nf][2] + p1.x) * SCALE;
            float s11 = (sacc[nf][3] + p1.y) * SCALE;
            sacc[nf][0] = (jc     <= gi0 + 512) ? s00 : -1e30f;
            sacc[nf][1] = (jc + 1 <= gi0 + 512) ? s01 : -1e30f;
            sacc[nf][2] = (jc     <= gi1 + 512) ? s10 : -1e30f;
            sacc[nf][3] = (jc + 1 <= gi1 + 512) ? s11 : -1e30f;
            mnew0 = fmaxf(mnew0, fmaxf(sacc[nf][0], sacc[nf][1]));
            mnew1 = fmaxf(mnew1, fmaxf(sacc[nf][2], sacc[nf][3]));
        }
#pragma unroll
        for (int d = 1; d < 4; d <<= 1) {
            mnew0 = fmaxf(mnew0, __shfl_xor_sync(0xffffffffu, mnew0, d));
            mnew1 = fmaxf(mnew1, __shfl_xor_sync(0xffffffffu, mnew1, d));
        }
        float fs0 = __expf(mrow0 - mnew0);
        float fs1 = __expf(mrow1 - mnew1);
        mrow0 = mnew0; mrow1 = mnew1;
        float ps0 = 0.f, ps1 = 0.f;
#pragma unroll
        for (int nf = 0; nf < 8; ++nf) {
            sacc[nf][0] = __expf(sacc[nf][0] - mnew0);
            sacc[nf][1] = __expf(sacc[nf][1] - mnew0);
            sacc[nf][2] = __expf(sacc[nf][2] - mnew1);
            sacc[nf][3] = __expf(sacc[nf][3] - mnew1);
            ps0 += sacc[nf][0] + sacc[nf][1];
            ps1 += sacc[nf][2] + sacc[nf][3];
        }
#pragma unroll
        for (int d = 1; d < 4; d <<= 1) {
            ps0 += __shfl_xor_sync(0xffffffffu, ps0, d);
            ps1 += __shfl_xor_sync(0xffffffffu, ps1, d);
        }
        lrow0 = lrow0 * fs0 + ps0;
        lrow1 = lrow1 * fs1 + ps1;
#pragma unroll
        for (int nf = 0; nf < 16; ++nf) {
            of[nf][0] *= fs0; of[nf][1] *= fs0;
            of[nf][2] *= fs1; of[nf][3] *= fs1;
        }

        // store P to warp-private sP rows (tf32, swizzled)
#pragma unroll
        for (int nf = 0; nf < 8; ++nf)
#pragma unroll
            for (int e = 0; e < 4; ++e) {
                int row = w * 16 + r0l + ((e >= 2) ? 8 : 0);
                int c = nf * 8 + c0l + (e & 1);
                int seg = c >> 5, cc = c & 31;
                sP[seg * 4096 + row * 32 + (((cc >> 2) ^ (row & 7)) << 2) + (cc & 3)] = f2tf(sacc[nf][e]);
            }
        __syncwarp();

        // O += P V^T
#pragma unroll
        for (int kseg = 0; kseg < 2; ++kseg)
#pragma unroll
            for (int ks = 0; ks < 4; ++ks) {
                uint32_t pa[4];
                {
                    int row = w * 16 + ((lm & 1) << 3) + lrow;
                    int ch = ks * 2 + (lm >> 1);
                    ldsm4(pa[0], pa[1], pa[2], pa[3],
                          sPb + ((kseg * 4096 + row * 32 + ((ch ^ lrow) << 2)) << 2));
                }
#pragma unroll
                for (int nbh = 0; nbh < 2; ++nbh) {
                    uint32_t bv[4][4];
#pragma unroll
                    for (int nb = 0; nb < 4; ++nb) {
                        int row = (nbh * 4 + nb) * 16 + ((lm >> 1) << 3) + lrow;
                        int ch = ks * 2 + (lm & 1);
                        ldsm4(bv[nb][0], bv[nb][1], bv[nb][2], bv[nb][3],
                              sVb + ((kseg * 4096 + row * 32 + ((ch ^ lrow) << 2)) << 2));
                    }
#pragma unroll
                    for (int nf = 0; nf < 8; ++nf)
                        mma8(of[nbh * 8 + nf], pa, bv[nf >> 1][(nf & 1) * 2], bv[nf >> 1][(nf & 1) * 2 + 1]);
                }
            }
        __syncthreads();
    }

    // normalize + write O
    float inv0 = 1.f / lrow0, inv1 = 1.f / lrow1;
    int b = bh >> 3, h = bh & 7;
#pragma unroll
    for (int nf = 0; nf < 16; ++nf) {
        int d = nf * 8 + c0l;
        float2 v0 = make_float2(of[nf][0] * inv0, of[nf][1] * inv0);
        float2 v1 = make_float2(of[nf][2] * inv1, of[nf][3] * inv1);
        *(float2*)&g_O[(size_t)(gi0 * 16 + b) * 1024 + h * 128 + d] = v0;
        *(float2*)&g_O[(size_t)(gi1 * 16 + b) * 1024 + h * 128 + d] = v1;
    }
}

__global__ void copy_k(const float* __restrict__ src, float* __restrict__ dst) {
    int idx = blockIdx.x * blockDim.x + threadIdx.x;
    ((float4*)dst)[idx] = ((const float4*)src)[idx];
}

extern "C" void kernel_launch(void* const* d_in, const int* in_sizes, int n_in,
                              void* d_out, int out_size) {
    const float* inputs = (const float*)d_in[0];
    const float* memory = (const float*)d_in[1];
    const float* w_kv   = (const float*)d_in[2];
    const float* w_q    = (const float*)d_in[3];
    const float* w_p    = (const float*)d_in[4];
    const float* w_out  = (const float*)d_in[5];
    const float* u      = (const float*)d_in[6];
    const float* v      = (const float*)d_in[7];
    float* out = (float*)d_out;

    int writeAux = (out_size >= 3 * 1048576) ? 1 : 0;

    cudaFuncSetAttribute(flash_k, cudaFuncAttributeMaxDynamicSharedMemorySize, 98304);

    pe_fill<<<256, 256>>>();
    // kv proj: M=16384, N=2048, K=128
    gemm_k<0><<<dim3(32, 128, 1), 256>>>(inputs, memory, w_kv, nullptr, nullptr, nullptr, 0);
    // q proj: M=8192, N=1024, K=128
    gemm_k<1><<<dim3(16, 64, 1), 256>>>(inputs, nullptr, w_q, u, v, nullptr, 0);
    // p proj: M=1024, N=1024, K=128
    gemm_k<2><<<dim3(16, 8, 1), 256>>>(inputs, nullptr, w_p, nullptr, nullptr, nullptr, 0);
    // position scores (shifted epilogue): M=512, N=1024, K=128, z=128
    gemm_k<4><<<dim3(16, 4, 128), 256>>>(inputs, nullptr, nullptr, nullptr, nullptr, nullptr, 0);
    // fused flash attention: content scores + shift-add + softmax + PV
    flash_k<<<dim3(4, 128), 256, 98304>>>();
    // out proj: M=8192, N=128, K=1024
    gemm_k<6><<<dim3(2, 64, 1), 256>>>(inputs, nullptr, w_out, nullptr, nullptr, out, writeAux);
    if (writeAux) copy_k<<<1024, 256>>>(inputs, out + 1048576);
}

// round 5
// speedup vs baseline: 3.8802x; 1.2088x over previous
#include <cuda_runtime.h>
#include <cuda_fp16.h>
#include <math.h>
#include <stdint.h>

#define SCALE 0.088388347648318447f  // 1/sqrt(128)

// ---- static scratch (allocation-free), fp16 intermediates ----
__device__ __half g_K  [16777216];   // [b,h,j,d]
__device__ __half g_Vt [16777216];   // [b,h,d,j]
__device__ __half g_QU [8388608];    // [b,h,i,d]  q+u
__device__ __half g_QV [8388608];    // [b,h,i,d]  q+v
__device__ __half g_P  [1048576];    // [h,jj,d]
__device__ __half g_S2 [67108864];   // [bh,i,j]   shifted position scores (valid j<=i+512)
__device__ __half g_O  [8388608];    // [i*B+b, h*128+d]
__device__ float  g_PE [131072];     // [jj,e]

__global__ void pe_fill() {
    int idx = blockIdx.x * blockDim.x + threadIdx.x;
    if (idx >= 65536) return;
    int jj = idx >> 6, e2 = idx & 63;
    double pos  = (double)(1023 - jj);
    double invf = exp(-((double)e2 / 64.0) * log(10000.0));
    double ang  = pos * invf;
    g_PE[jj * 128 + e2]      = (float)sin(ang);
    g_PE[jj * 128 + 64 + e2] = (float)cos(ang);
}

__device__ __forceinline__ uint32_t f2h2(float a, float b) {
    __half2 h = __floats2half2_rn(a, b);
    return *reinterpret_cast<uint32_t*>(&h);
}
__device__ __forceinline__ void ldsm4(uint32_t& r0, uint32_t& r1, uint32_t& r2, uint32_t& r3, uint32_t addr) {
    asm volatile("ldmatrix.sync.aligned.m8n8.x4.shared.b16 {%0,%1,%2,%3}, [%4];"
                 : "=r"(r0), "=r"(r1), "=r"(r2), "=r"(r3) : "r"(addr));
}
__device__ __forceinline__ void mma16(float* c, const uint32_t* a, uint32_t b0, uint32_t b1) {
    asm volatile("mma.sync.aligned.m16n8k16.row.col.f32.f16.f16.f32 "
                 "{%0,%1,%2,%3},{%4,%5,%6,%7},{%8,%9},{%0,%1,%2,%3};"
                 : "+f"(c[0]), "+f"(c[1]), "+f"(c[2]), "+f"(c[3])
                 : "r"(a[0]), "r"(a[1]), "r"(a[2]), "r"(a[3]), "r"(b0), "r"(b1));
}

// ---- fp16 tensor-core NT GEMM: C[M,N] = A[M,K] * W[N,K]^T ----
// BM=128, BN=64, BK=64 halves; 8 warps, each 32x32 via m16n8k16.
// MODE 0: kv proj   MODE 1: q proj   MODE 2: p proj
// MODE 4: position scores (rel-shift epilogue)   MODE 6: out proj
template<int MODE>
__global__ void __launch_bounds__(256) gemm_k(
    const float* __restrict__ inputs, const float* __restrict__ mem0,
    const float* __restrict__ Wext, const float* __restrict__ uu,
    const float* __restrict__ vv, float* __restrict__ dout, int writeAux)
{
    constexpr int K   = (MODE >= 5) ? 1024 : 128;  // elements
    constexpr int KIT = K / 64;
    constexpr bool AF32 = (MODE <= 2);
    constexpr bool BF32 = (MODE <= 2 || MODE == 6);
    const int z  = blockIdx.z;
    const int m0 = blockIdx.y * 128, n0 = blockIdx.x * 64;
    if (MODE == 4 && m0 + n0 + 190 < 511) return;  // fully outside used band
    const int tid = threadIdx.x;
    const int lane = tid & 31, w = tid >> 5;
    const int wm = w >> 1, wn = w & 1;

    const float* Af = nullptr;
    const __half* Ah = nullptr;
    const float* Bf = Wext;
    const __half* Bh = nullptr;
    if (MODE == 1) Af = inputs;
    if (MODE == 2) Af = g_PE;
    if (MODE == 4) { Ah = g_QV + (size_t)z * 65536;  Bh = g_P + (size_t)(z & 7) * 131072; }
    if (MODE == 6) { Ah = g_O; }

    __shared__ uint32_t As[4096];  // 128 rows x 32 u32 (64 halves), swizzled 16B chunks
    __shared__ uint32_t Bs[2048];  // 64 rows x 32 u32
    uint32_t as_addr = (uint32_t)__cvta_generic_to_shared(As);
    uint32_t bs_addr = (uint32_t)__cvta_generic_to_shared(Bs);

    float acc[2][4][4];
#pragma unroll
    for (int a = 0; a < 2; ++a)
#pragma unroll
        for (int b = 0; b < 4; ++b)
#pragma unroll
            for (int c = 0; c < 4; ++c) acc[a][b][c] = 0.f;

    float4 pa32[4][2], pb32[2][2];
    uint4 pa16[4], pb16[2];

    auto loadA = [&](int it) {
#pragma unroll
        for (int i = 0; i < 4; ++i) {
            int idx = tid + i * 256;
            int row = idx >> 3, ch = idx & 7;
            int r = m0 + row;
            if (AF32) {
                const float* Ap;
                if (MODE == 0)
                    Ap = (r < 8192) ? (mem0 + (size_t)r * 128)
                                    : (inputs + (size_t)(r - 8192) * 128);
                else
                    Ap = Af + (size_t)r * K;
                pa32[i][0] = *(const float4*)(Ap + it * 64 + ch * 8);
                pa32[i][1] = *(const float4*)(Ap + it * 64 + ch * 8 + 4);
            } else {
                pa16[i] = *(const uint4*)(Ah + (size_t)r * K + it * 64 + ch * 8);
            }
        }
    };
    auto loadB = [&](int it) {
#pragma unroll
        for (int i = 0; i < 2; ++i) {
            int idx = tid + i * 256;
            int row = idx >> 3, ch = idx & 7;
            if (BF32) {
                pb32[i][0] = *(const float4*)(Bf + (size_t)(n0 + row) * K + it * 64 + ch * 8);
                pb32[i][1] = *(const float4*)(Bf + (size_t)(n0 + row) * K + it * 64 + ch * 8 + 4);
            } else {
                pb16[i] = *(const uint4*)(Bh + (size_t)(n0 + row) * K + it * 64 + ch * 8);
            }
        }
    };
    auto stage = [&]() {
#pragma unroll
        for (int i = 0; i < 4; ++i) {
            int idx = tid + i * 256;
            int row = idx >> 3, ch = idx & 7;
            uint32_t off = row * 32 + ((ch ^ (row & 7)) << 2);
            uint4 v;
            if (AF32) v = make_uint4(f2h2(pa32[i][0].x, pa32[i][0].y), f2h2(pa32[i][0].z, pa32[i][0].w),
                                     f2h2(pa32[i][1].x, pa32[i][1].y), f2h2(pa32[i][1].z, pa32[i][1].w));
            else v = pa16[i];
            *(uint4*)&As[off] = v;
        }
#pragma unroll
        for (int i = 0; i < 2; ++i) {
            int idx = tid + i * 256;
            int row = idx >> 3, ch = idx & 7;
            uint32_t off = row * 32 + ((ch ^ (row & 7)) << 2);
            uint4 v;
            if (BF32) v = make_uint4(f2h2(pb32[i][0].x, pb32[i][0].y), f2h2(pb32[i][0].z, pb32[i][0].w),
                                     f2h2(pb32[i][1].x, pb32[i][1].y), f2h2(pb32[i][1].z, pb32[i][1].w));
            else v = pb16[i];
            *(uint4*)&Bs[off] = v;
        }
    };

    loadA(0); loadB(0);
    stage();
    __syncthreads();

    const int lrow = lane & 7, lm = lane >> 3;
    for (int it = 0; it < KIT; ++it) {
        if (it + 1 < KIT) { loadA(it + 1); loadB(it + 1); }
#pragma unroll
        for (int ks = 0; ks < 4; ++ks) {  // k16 steps within BK=64
            uint32_t afr[2][4], bfr[2][4];
#pragma unroll
            for (int mi = 0; mi < 2; ++mi) {
                int row = wm * 32 + mi * 16 + ((lm & 1) << 3) + lrow;
                int ch  = ks * 2 + (lm >> 1);
                ldsm4(afr[mi][0], afr[mi][1], afr[mi][2], afr[mi][3],
                      as_addr + ((row * 32 + ((ch ^ lrow) << 2)) << 2));
            }
#pragma unroll
            for (int np = 0; np < 2; ++np) {
                int row = wn * 32 + np * 16 + ((lm >> 1) << 3) + lrow;
                int ch  = ks * 2 + (lm & 1);
                ldsm4(bfr[np][0], bfr[np][1], bfr[np][2], bfr[np][3],
                      bs_addr + ((row * 32 + ((ch ^ lrow) << 2)) << 2));
            }
#pragma unroll
            for (int mi = 0; mi < 2; ++mi)
#pragma unroll
                for (int nj = 0; nj < 4; ++nj)
                    mma16(acc[mi][nj], afr[mi], bfr[nj >> 1][(nj & 1) * 2], bfr[nj >> 1][(nj & 1) * 2 + 1]);
        }
        __syncthreads();
        if (it + 1 < KIT) { stage(); __syncthreads(); }
    }

    // ---- epilogue ----
    const int r0l = lane >> 2, c0l = (lane & 3) * 2;
#pragma unroll
    for (int mi = 0; mi < 2; ++mi)
#pragma unroll
        for (int nj = 0; nj < 4; ++nj)
#pragma unroll
            for (int e = 0; e < 4; ++e) {
                int r = m0 + wm * 32 + mi * 16 + r0l + ((e >= 2) ? 8 : 0);
                int n = n0 + wn * 32 + nj * 8 + c0l + (e & 1);
                float val = acc[mi][nj][e];
                if (MODE == 0) {
                    int j = r >> 4, b = r & 15;
                    if (n < 1024) {
                        int h = n >> 7, d = n & 127;
                        g_K[(size_t)((b * 8 + h) * 1024 + j) * 128 + d] = __float2half(val);
                    } else {
                        int n2 = n - 1024; int h = n2 >> 7, d = n2 & 127;
                        g_Vt[(size_t)((b * 8 + h) * 128 + d) * 1024 + j] = __float2half(val);
                    }
                } else if (MODE == 1) {
                    int i = r >> 4, b = r & 15;
                    size_t base = (size_t)((b * 8 + (n >> 7)) * 512 + i) * 128 + (n & 127);
                    g_QU[base] = __float2half(val + uu[n]);
                    g_QV[base] = __float2half(val + vv[n]);
                } else if (MODE == 2) {
                    g_P[(size_t)((n >> 7) * 1024 + r) * 128 + (n & 127)] = __float2half(val);
                } else if (MODE == 4) {
                    int j = n - 511 + r;  // rel-shift: S2shift[i][j] = S2[i][511+j-i]
                    if (j >= 0 && j < 1024)
                        g_S2[(size_t)z * 524288 + (size_t)r * 1024 + j] = __float2half(val);
                } else {  // MODE 6
                    dout[(size_t)r * 128 + n] = val;
                    if (writeAux) dout[2097152 + (size_t)r * 128 + n] = val;
                }
            }
}

// ---- fused flash attention (fp16): S = QK^T + S2shift, masked online softmax, O = P V ----
__global__ void __launch_bounds__(256, 1) flash_k() {
    __shared__ uint32_t sK[4096];  // 2 segs x [64 rows x 32 u32] : K tile / Q staging
    __shared__ uint32_t sV[4096];  // 128 d-rows x 32 u32 (64 j halves)
    __shared__ uint32_t sP[4096];  // 128 i-rows x 32 u32 (64 j halves)
    const uint32_t sKb = (uint32_t)__cvta_generic_to_shared(sK);
    const uint32_t sVb = (uint32_t)__cvta_generic_to_shared(sV);
    const uint32_t sPb = (uint32_t)__cvta_generic_to_shared(sP);

    const int bh = blockIdx.y;
    const int i0 = blockIdx.x * 128;
    const int tid = threadIdx.x, lane = tid & 31, w = tid >> 5;
    const int lrow = lane & 7, lm = lane >> 3;
    const int r0l = lane >> 2, c0l = (lane & 3) * 2;

    const __half* Qb  = g_QU + (size_t)bh * 65536;
    const __half* Kb  = g_K  + (size_t)bh * 131072;
    const __half* Vb  = g_Vt + (size_t)bh * 131072;
    const __half* S2b = g_S2 + (size_t)bh * 524288;

    uint32_t qf[8][4];

    // ---- Q fragments via smem staging (two 64-row halves) ----
#pragma unroll
    for (int half = 0; half < 2; ++half) {
#pragma unroll
        for (int t = 0; t < 4; ++t) {
            int idx = tid + t * 256;
            int row = idx >> 4, c16 = idx & 15;
            int seg = c16 >> 3, ch = c16 & 7;
            uint4 v = *(const uint4*)(Qb + (size_t)(i0 + half * 64 + row) * 128 + c16 * 8);
            *(uint4*)&sK[seg * 2048 + row * 32 + ((ch ^ (row & 7)) << 2)] = v;
        }
        __syncthreads();
        if ((w >> 2) == half) {
            int wr = (w & 3) * 16;
#pragma unroll
            for (int ks = 0; ks < 8; ++ks) {
                int row = wr + ((lm & 1) << 3) + lrow;
                int seg = ks >> 2, ch = (ks & 3) * 2 + (lm >> 1);
                ldsm4(qf[ks][0], qf[ks][1], qf[ks][2], qf[ks][3],
                      sKb + ((seg * 2048 + row * 32 + ((ch ^ lrow) << 2)) << 2));
            }
        }
        __syncthreads();
    }

    float of[16][4];
#pragma unroll
    for (int a = 0; a < 16; ++a)
#pragma unroll
        for (int e = 0; e < 4; ++e) of[a][e] = 0.f;
    float mrow0 = -1e30f, mrow1 = -1e30f;
    float lrow0 = 0.f, lrow1 = 0.f;

    const int gi0 = i0 + w * 16 + r0l;
    const int gi1 = gi0 + 8;
    const int njt = 2 * blockIdx.x + 10;

    for (int jt = 0; jt < njt; ++jt) {
        int j0 = jt * 64;
        // K tile: 64 j-rows x 128 d halves
#pragma unroll
        for (int t = 0; t < 4; ++t) {
            int idx = tid + t * 256;
            int row = idx >> 4, c16 = idx & 15;
            int seg = c16 >> 3, ch = c16 & 7;
            uint4 v = *(const uint4*)(Kb + (size_t)(j0 + row) * 128 + c16 * 8);
            *(uint4*)&sK[seg * 2048 + row * 32 + ((ch ^ (row & 7)) << 2)] = v;
        }
        // V^T tile: 128 d-rows x 64 j halves
#pragma unroll
        for (int t = 0; t < 4; ++t) {
            int idx = tid + t * 256;
            int row = idx >> 3, ch = idx & 7;
            uint4 v = *(const uint4*)(Vb + (size_t)row * 1024 + j0 + ch * 8);
            *(uint4*)&sV[row * 32 + ((ch ^ (row & 7)) << 2)] = v;
        }
        __syncthreads();

        // scores: S = Q K^T (16 x 64 per warp)
        float sacc[8][4];
#pragma unroll
        for (int a = 0; a < 8; ++a)
#pragma unroll
            for (int e = 0; e < 4; ++e) sacc[a][e] = 0.f;
#pragma unroll
        for (int ks = 0; ks < 8; ++ks) {
            uint32_t bfr[4][4];
#pragma unroll
            for (int nb = 0; nb < 4; ++nb) {
                int row = nb * 16 + ((lm >> 1) << 3) + lrow;
                int seg = ks >> 2, ch = (ks & 3) * 2 + (lm & 1);
                ldsm4(bfr[nb][0], bfr[nb][1], bfr[nb][2], bfr[nb][3],
                      sKb + ((seg * 2048 + row * 32 + ((ch ^ lrow) << 2)) << 2));
            }
#pragma unroll
            for (int nf = 0; nf < 8; ++nf)
                mma16(sacc[nf], qf[ks], bfr[nf >> 1][(nf & 1) * 2], bfr[nf >> 1][(nf & 1) * 2 + 1]);
        }

        // add shifted position scores, mask, scale, online softmax
        float mnew0 = mrow0, mnew1 = mrow1;
#pragma unroll
        for (int nf = 0; nf < 8; ++nf) {
            int jc = j0 + nf * 8 + c0l;
            float2 p0 = __half22float2(*(const __half2*)(S2b + (size_t)gi0 * 1024 + jc));
            float2 p1 = __half22float2(*(const __half2*)(S2b + (size_t)gi1 * 1024 + jc));
            float s00 = (sacc[nf][0] + p0.x) * SCALE;
            float s01 = (sacc[nf][1] + p0.y) * SCALE;
            float s10 = (sacc[nf][2] + p1.x) * SCALE;
            float s11 = (sacc[nf][3] + p1.y) * SCALE;
            sacc[nf][0] = (jc     <= gi0 + 512) ? s00 : -1e30f;
            sacc[nf][1] = (jc + 1 <= gi0 + 512) ? s01 : -1e30f;
            sacc[nf][2] = (jc     <= gi1 + 512) ? s10 : -1e30f;
            sacc[nf][3] = (jc + 1 <= gi1 + 512) ? s11 : -1e30f;
            mnew0 = fmaxf(mnew0, fmaxf(sacc[nf][0], sacc[nf][1]));
            mnew1 = fmaxf(mnew1, fmaxf(sacc[nf][2], sacc[nf][3]));
        }
#pragma unroll
        for (int d = 1; d < 4; d <<= 1) {
            mnew0 = fmaxf(mnew0, __shfl_xor_sync(0xffffffffu, mnew0, d));
            mnew1 = fmaxf(mnew1, __shfl_xor_sync(0xffffffffu, mnew1, d));
        }
        float fs0 = __expf(mrow0 - mnew0);
        float fs1 = __expf(mrow1 - mnew1);
        mrow0 = mnew0; mrow1 = mnew1;
        float ps0 = 0.f, ps1 = 0.f;
#pragma unroll
        for (int nf = 0; nf < 8; ++nf) {
            sacc[nf][0] = __expf(sacc[nf][0] - mnew0);
            sacc[nf][1] = __expf(sacc[nf][1] - mnew0);
            sacc[nf][2] = __expf(sacc[nf][2] - mnew1);
            sacc[nf][3] = __expf(sacc[nf][3] - mnew1);
            ps0 += sacc[nf][0] + sacc[nf][1];
            ps1 += sacc[nf][2] + sacc[nf][3];
        }
#pragma unroll
        for (int d = 1; d < 4; d <<= 1) {
            ps0 += __shfl_xor_sync(0xffffffffu, ps0, d);
            ps1 += __shfl_xor_sync(0xffffffffu, ps1, d);
        }
        lrow0 = lrow0 * fs0 + ps0;
        lrow1 = lrow1 * fs1 + ps1;
#pragma unroll
        for (int nf = 0; nf < 16; ++nf) {
            of[nf][0] *= fs0; of[nf][1] *= fs0;
            of[nf][2] *= fs1; of[nf][3] *= fs1;
        }

        // store P to warp-private sP rows (fp16 pairs, swizzled)
#pragma unroll
        for (int nf = 0; nf < 8; ++nf) {
            int c  = nf * 8 + c0l;            // even half-column
            int ch = c >> 3, wi = (c >> 1) & 3;
            int row0 = w * 16 + r0l;
            sP[row0 * 32 + ((ch ^ (row0 & 7)) << 2) + wi] = f2h2(sacc[nf][0], sacc[nf][1]);
            int row1 = row0 + 8;
            sP[row1 * 32 + ((ch ^ (row1 & 7)) << 2) + wi] = f2h2(sacc[nf][2], sacc[nf][3]);
        }
        __syncwarp();

        // O += P V^T
#pragma unroll
        for (int ks = 0; ks < 4; ++ks) {
            uint32_t pa[4];
            {
                int row = w * 16 + ((lm & 1) << 3) + lrow;
                int ch  = ks * 2 + (lm >> 1);
                ldsm4(pa[0], pa[1], pa[2], pa[3],
                      sPb + ((row * 32 + ((ch ^ lrow) << 2)) << 2));
            }
#pragma unroll
            for (int nb = 0; nb < 8; ++nb) {
                uint32_t bv[4];
                int rowb = nb * 16 + ((lm >> 1) << 3) + lrow;
                int chb  = ks * 2 + (lm & 1);
                ldsm4(bv[0], bv[1], bv[2], bv[3],
                      sVb + ((rowb * 32 + ((chb ^ lrow) << 2)) << 2));
                mma16(of[nb * 2],     pa, bv[0], bv[1]);
                mma16(of[nb * 2 + 1], pa, bv[2], bv[3]);
            }
        }
        __syncthreads();
    }

    // normalize + write O (fp16)
    float inv0 = 1.f / lrow0, inv1 = 1.f / lrow1;
    int b = bh >> 3, h = bh & 7;
#pragma unroll
    for (int nf = 0; nf < 16; ++nf) {
        int d = nf * 8 + c0l;
        *(uint32_t*)&g_O[(size_t)(gi0 * 16 + b) * 1024 + h * 128 + d] = f2h2(of[nf][0] * inv0, of[nf][1] * inv0);
        *(uint32_t*)&g_O[(size_t)(gi1 * 16 + b) * 1024 + h * 128 + d] = f2h2(of[nf][2] * inv1, of[nf][3] * inv1);
    }
}

__global__ void copy_k(const float* __restrict__ src, float* __restrict__ dst) {
    int idx = blockIdx.x * blockDim.x + threadIdx.x;
    ((float4*)dst)[idx] = ((const float4*)src)[idx];
}

extern "C" void kernel_launch(void* const* d_in, const int* in_sizes, int n_in,
                              void* d_out, int out_size) {
    const float* inputs = (const float*)d_in[0];
    const float* memory = (const float*)d_in[1];
    const float* w_kv   = (const float*)d_in[2];
    const float* w_q    = (const float*)d_in[3];
    const float* w_p    = (const float*)d_in[4];
    const float* w_out  = (const float*)d_in[5];
    const float* u      = (const float*)d_in[6];
    const float* v      = (const float*)d_in[7];
    float* out = (float*)d_out;

    int writeAux = (out_size >= 3 * 1048576) ? 1 : 0;

    pe_fill<<<256, 256>>>();
    // kv proj: M=16384, N=2048, K=128
    gemm_k<0><<<dim3(32, 128, 1), 256>>>(inputs, memory, w_kv, nullptr, nullptr, nullptr, 0);
    // q proj: M=8192, N=1024, K=128
    gemm_k<1><<<dim3(16, 64, 1), 256>>>(inputs, nullptr, w_q, u, v, nullptr, 0);
    // p proj: M=1024, N=1024, K=128
    gemm_k<2><<<dim3(16, 8, 1), 256>>>(inputs, nullptr, w_p, nullptr, nullptr, nullptr, 0);
    // position scores (shifted epilogue): M=512, N=1024, K=128, z=128
    gemm_k<4><<<dim3(16, 4, 128), 256>>>(inputs, nullptr, nullptr, nullptr, nullptr, nullptr, 0);
    // fused flash attention
    flash_k<<<dim3(4, 128), 256>>>();
    // out proj: M=8192, N=128, K=1024
    gemm_k<6><<<dim3(2, 64, 1), 256>>>(inputs, nullptr, w_out, nullptr, nullptr, out, writeAux);
    if (writeAux) copy_k<<<1024, 256>>>(inputs, out + 1048576);
}